// round 1
// baseline (speedup 1.0000x reference)
#include <cuda_runtime.h>

// Hierarchical 2-additive Choquet integral, B=16, DEPTH=6.
// One warp per node. Level l: out[node] = sum_k softmax(theta)[k] * v_k
// where v_k = x[k] for k<16, v_k = min(x[i],x[j]) for pair k-16.

#define B16 16
#define NPAIR 120
#define NTH 136   // B16 + NPAIR

// (i,j) table: k<16 -> (k,k) so min(x_i,x_j)=x_k; k>=16 -> triu pair (row-major).
__constant__ unsigned char c_II[NTH] = {
    0,1,2,3,4,5,6,7,8,9,10,11,12,13,14,15,
    // i=0 (15)
    0,0,0,0,0,0,0,0,0,0,0,0,0,0,0,
    // i=1 (14)
    1,1,1,1,1,1,1,1,1,1,1,1,1,1,
    // i=2 (13)
    2,2,2,2,2,2,2,2,2,2,2,2,2,
    // i=3 (12)
    3,3,3,3,3,3,3,3,3,3,3,3,
    // i=4 (11)
    4,4,4,4,4,4,4,4,4,4,4,
    // i=5 (10)
    5,5,5,5,5,5,5,5,5,5,
    // i=6 (9)
    6,6,6,6,6,6,6,6,6,
    // i=7 (8)
    7,7,7,7,7,7,7,7,
    // i=8 (7)
    8,8,8,8,8,8,8,
    // i=9 (6)
    9,9,9,9,9,9,
    // i=10 (5)
    10,10,10,10,10,
    // i=11 (4)
    11,11,11,11,
    // i=12 (3)
    12,12,12,
    // i=13 (2)
    13,13,
    // i=14 (1)
    14
};
__constant__ unsigned char c_JJ[NTH] = {
    0,1,2,3,4,5,6,7,8,9,10,11,12,13,14,15,
    // i=0: j=1..15
    1,2,3,4,5,6,7,8,9,10,11,12,13,14,15,
    // i=1: j=2..15
    2,3,4,5,6,7,8,9,10,11,12,13,14,15,
    // i=2: j=3..15
    3,4,5,6,7,8,9,10,11,12,13,14,15,
    // i=3: j=4..15
    4,5,6,7,8,9,10,11,12,13,14,15,
    // i=4: j=5..15
    5,6,7,8,9,10,11,12,13,14,15,
    // i=5: j=6..15
    6,7,8,9,10,11,12,13,14,15,
    // i=6: j=7..15
    7,8,9,10,11,12,13,14,15,
    // i=7: j=8..15
    8,9,10,11,12,13,14,15,
    // i=8: j=9..15
    9,10,11,12,13,14,15,
    // i=9: j=10..15
    10,11,12,13,14,15,
    // i=10: j=11..15
    11,12,13,14,15,
    // i=11: j=12..15
    12,13,14,15,
    // i=12: j=13..15
    13,14,15,
    // i=13: j=14,15
    14,15,
    // i=14: j=15
    15
};

// Ping-pong scratch for intermediate level outputs (max 16^5 = 1,048,576 floats).
__device__ float g_buf0[1 << 20];
__device__ float g_buf1[1 << 16];

__global__ void __launch_bounds__(256)
choquet_level_kernel(const float* __restrict__ vals,
                     const float* __restrict__ theta,
                     float* __restrict__ out,
                     int n_nodes)
{
    const int gwarp = (int)((blockIdx.x * blockDim.x + threadIdx.x) >> 5);
    const int lane  = threadIdx.x & 31;
    if (gwarp >= n_nodes) return;

    // lanes 0..15 hold the 16 child values of this node
    float xv = 0.f;
    if (lane < B16) xv = vals[gwarp * B16 + lane];

    const float* th = theta + (size_t)gwarp * NTH;

    float num = 0.f, den = 0.f;

#pragma unroll
    for (int t = 0; t < 5; ++t) {
        const int k = lane + 32 * t;
        const bool act = (k < NTH);           // last pass: 8 active lanes
        const float tv = act ? __ldg(&th[k]) : 0.f;
        const int i = act ? (int)c_II[k] : 0;
        const int j = act ? (int)c_JJ[k] : 0;
        const float a = __shfl_sync(0xffffffffu, xv, i);
        const float b = __shfl_sync(0xffffffffu, xv, j);
        const float v = fminf(a, b);
        const float e = act ? __expf(tv) : 0.f;
        den += e;
        num += e * v;
    }

    // butterfly reduction across warp
#pragma unroll
    for (int o = 16; o > 0; o >>= 1) {
        num += __shfl_xor_sync(0xffffffffu, num, o);
        den += __shfl_xor_sync(0xffffffffu, den, o);
    }

    if (lane == 0) out[gwarp] = num / den;
}

static inline void launch_level(const float* vals, const float* theta,
                                float* out, int n_nodes)
{
    const int threads = 256;                 // 8 warps/block
    const int warps_per_block = threads / 32;
    const int blocks = (n_nodes + warps_per_block - 1) / warps_per_block;
    choquet_level_kernel<<<blocks, threads>>>(vals, theta, out, n_nodes);
}

extern "C" void kernel_launch(void* const* d_in, const int* in_sizes, int n_in,
                              void* d_out, int out_size)
{
    (void)in_sizes; (void)n_in; (void)out_size;

    const float* x = (const float*)d_in[0];
    const float* th1 = (const float*)d_in[1];
    const float* th2 = (const float*)d_in[2];
    const float* th3 = (const float*)d_in[3];
    const float* th4 = (const float*)d_in[4];
    const float* th5 = (const float*)d_in[5];
    const float* th6 = (const float*)d_in[6];
    float* out = (float*)d_out;

    float *b0, *b1;
    cudaGetSymbolAddress((void**)&b0, g_buf0);
    cudaGetSymbolAddress((void**)&b1, g_buf1);

    // level node counts: 16^5, 16^4, 16^3, 16^2, 16, 1
    launch_level(x,  th1, b0, 1 << 20);   // 1,048,576 nodes
    launch_level(b0, th2, b1, 1 << 16);   // 65,536
    launch_level(b1, th3, b0, 1 << 12);   // 4,096
    launch_level(b0, th4, b1, 1 << 8);    // 256
    launch_level(b1, th5, b0, 16);        // 16
    launch_level(b0, th6, out, 1);        // 1 -> d_out
}

// round 2
// speedup vs baseline: 14.1587x; 14.1587x over previous
#include <cuda_runtime.h>

// Hierarchical 2-additive Choquet integral, B=16, DEPTH=6.
// Levels 1-3 (1M, 64K, 4K nodes): one warp per node, smem pair-LUT (no divergent LDC).
// Levels 4-6 (256, 16, 1 nodes): fused single-block kernel, thread-per-node, unrolled.

#define B16 16
#define NPAIR 120
#define NTH 136   // B16 + NPAIR

// Ping-pong scratch for intermediate level outputs.
__device__ float g_buf0[1 << 20];
__device__ float g_buf1[1 << 16];

// ---------------------------------------------------------------------------
// Big-level kernel: one warp per node.
// lut[k] packs (i | j<<8); k<16 -> (k,k) so fmin(x_i,x_j)=x_k (branchless singleton).
// ---------------------------------------------------------------------------
__global__ void __launch_bounds__(256)
choquet_level_kernel(const float* __restrict__ vals,
                     const float* __restrict__ theta,
                     float* __restrict__ out,
                     int n_nodes)
{
    __shared__ int s_lut[NTH];

    // Arithmetic fill — no constant-memory reads, no divergent-LDC serialization.
    {
        const int t = threadIdx.x;
        if (t < NTH) {
            int i, j;
            if (t < B16) {
                i = t; j = t;
            } else {
                int rem = t - B16;
                i = 0;
                #pragma unroll 1
                while (rem >= 15 - i) { rem -= 15 - i; ++i; }
                j = i + 1 + rem;
            }
            s_lut[t] = i | (j << 8);
        }
    }
    __syncthreads();

    const int gwarp = (int)((blockIdx.x * blockDim.x + threadIdx.x) >> 5);
    const int lane  = threadIdx.x & 31;
    if (gwarp >= n_nodes) return;

    // lanes 0..15 hold the 16 child values of this node
    float xv = 0.f;
    if (lane < B16) xv = __ldg(&vals[gwarp * B16 + lane]);

    const float* th = theta + (size_t)gwarp * NTH;

    float num = 0.f, den = 0.f;

#pragma unroll
    for (int t = 0; t < 5; ++t) {
        const int k   = lane + 32 * t;
        const bool act = (k < NTH);               // last pass: 8 active lanes
        const int kk  = act ? k : (NTH - 1);
        const float tv = act ? __ldg(&th[kk]) : 0.f;
        const int p = s_lut[kk];                  // bank = kk%32 = lane: conflict-free
        const int i = p & 0xff;
        const int j = p >> 8;
        const float a = __shfl_sync(0xffffffffu, xv, i);
        const float b = __shfl_sync(0xffffffffu, xv, j);
        const float v = fminf(a, b);
        const float e = act ? __expf(tv) : 0.f;
        den += e;
        num = fmaf(e, v, num);
    }

    // butterfly reduction across warp
#pragma unroll
    for (int o = 16; o > 0; o >>= 1) {
        num += __shfl_xor_sync(0xffffffffu, num, o);
        den += __shfl_xor_sync(0xffffffffu, den, o);
    }

    if (lane == 0) out[gwarp] = num / den;
}

// ---------------------------------------------------------------------------
// Tail: levels 4,5,6 fused in one block (256 -> 16 -> 1 nodes), thread-per-node.
// Pair indices are compile-time (fully unrolled) -> no LUT at all.
// ---------------------------------------------------------------------------
__device__ __forceinline__ float node_eval(const float* __restrict__ xs_src,
                                           const float* __restrict__ th)
{
    float xs[B16];
#pragma unroll
    for (int c = 0; c < B16; ++c) xs[c] = xs_src[c];

    float num = 0.f, den = 0.f;
#pragma unroll
    for (int k = 0; k < B16; ++k) {
        const float e = __expf(th[k]);
        den += e;
        num = fmaf(e, xs[k], num);
    }
    int p = B16;
#pragma unroll
    for (int i = 0; i < B16 - 1; ++i) {
#pragma unroll
        for (int j = i + 1; j < B16; ++j) {
            const float e = __expf(th[p++]);
            den += e;
            num = fmaf(e, fminf(xs[i], xs[j]), num);
        }
    }
    return num / den;
}

__global__ void __launch_bounds__(256)
choquet_tail_kernel(const float* __restrict__ v3,     // 4096 level-3 outputs
                    const float* __restrict__ th4,    // 256 x 136
                    const float* __restrict__ th5,    // 16 x 136
                    const float* __restrict__ th6,    // 1 x 136
                    float* __restrict__ out)
{
    __shared__ float s4[256];
    __shared__ float s5[16];
    const int t = threadIdx.x;

    // level 4: 256 nodes
    s4[t] = node_eval(&v3[t * B16], &th4[(size_t)t * NTH]);
    __syncthreads();

    // level 5: 16 nodes
    if (t < 16) s5[t] = node_eval(&s4[t * B16], &th5[(size_t)t * NTH]);
    __syncthreads();

    // level 6: root
    if (t == 0) out[0] = node_eval(s5, th6);
}

static inline void launch_level(const float* vals, const float* theta,
                                float* out, int n_nodes)
{
    const int threads = 256;                 // 8 warps/block
    const int warps_per_block = threads / 32;
    const int blocks = (n_nodes + warps_per_block - 1) / warps_per_block;
    choquet_level_kernel<<<blocks, threads>>>(vals, theta, out, n_nodes);
}

extern "C" void kernel_launch(void* const* d_in, const int* in_sizes, int n_in,
                              void* d_out, int out_size)
{
    (void)in_sizes; (void)n_in; (void)out_size;

    const float* x   = (const float*)d_in[0];
    const float* th1 = (const float*)d_in[1];
    const float* th2 = (const float*)d_in[2];
    const float* th3 = (const float*)d_in[3];
    const float* th4 = (const float*)d_in[4];
    const float* th5 = (const float*)d_in[5];
    const float* th6 = (const float*)d_in[6];
    float* out = (float*)d_out;

    float *b0, *b1;
    cudaGetSymbolAddress((void**)&b0, g_buf0);
    cudaGetSymbolAddress((void**)&b1, g_buf1);

    launch_level(x,  th1, b0, 1 << 20);   // level 1: 1,048,576 nodes
    launch_level(b0, th2, b1, 1 << 16);   // level 2: 65,536
    launch_level(b1, th3, b0, 1 << 12);   // level 3: 4,096
    choquet_tail_kernel<<<1, 256>>>(b0, th4, th5, th6, out);   // levels 4-6
}

// round 4
// speedup vs baseline: 22.7787x; 1.6088x over previous
#include <cuda_runtime.h>

// Hierarchical 2-additive Choquet integral, B=16, DEPTH=6.
// Two nodes per warp: lanes 0-15 = node A children, lanes 16-31 = node B.
// Theta (136 per node) read as 32 float4 (vector passes) + 8 scalars (mini pass).
// Pair LUT: nibble-packed (i | j<<4) bytes, 4 per uint, built arithmetically in smem.

#define NTH 136

__device__ float g_buf0[1 << 20];
__device__ float g_buf1[1 << 16];

__device__ __forceinline__ void fill_lut(unsigned int* s_lut4)
{
    const int t = threadIdx.x;
    if (t < NTH) {
        int i, j;
        if (t < 16) { i = t; j = t; }           // singleton -> min(x_k,x_k)=x_k
        else {
            int rem = t - 16; i = 0;
            #pragma unroll 1
            while (rem >= 15 - i) { rem -= 15 - i; ++i; }
            j = i + 1 + rem;                    // triu row-major, matches np.triu_indices
        }
        ((unsigned char*)s_lut4)[t] = (unsigned char)(i | (j << 4));
    }
}

// Evaluate one node per 16-lane half-warp. xv: this lane's child value.
// th: this half's theta base (136 floats, 16B-aligned). Returns result on hl==0 lanes.
__device__ __forceinline__ float choquet_warp2(float xv, const float* __restrict__ th,
                                               const unsigned int* s_lut4)
{
    const int hl = threadIdx.x & 15;
    const float4* th4 = (const float4*)th;

    float num = 0.f, den = 0.f;

#pragma unroll
    for (int p = 0; p < 2; ++p) {                 // 2 vector passes: thetas 0..127
        const int q = hl + 16 * p;                // f4 index 0..31
        const float4 tv = __ldg(&th4[q]);
        const unsigned int pk = s_lut4[q];        // 4 packed (i|j<<4) bytes
#pragma unroll
        for (int e = 0; e < 4; ++e) {
            const float tvk = (e == 0) ? tv.x : (e == 1) ? tv.y : (e == 2) ? tv.z : tv.w;
            const int b = (pk >> (8 * e)) & 0xff;
            const float a = __shfl_sync(0xffffffffu, xv, b & 15, 16);
            const float c = __shfl_sync(0xffffffffu, xv, b >> 4, 16);
            const float ex = __expf(tvk);
            den += ex;
            num = fmaf(ex, fminf(a, c), num);
        }
    }

    // leftover thetas k = 128..135: lanes hl<8 handle one scalar each
    {
        const bool act = hl < 8;
        const int k = 128 + hl;
        const float tvk = act ? __ldg(&th[k]) : -1e30f;   // exp -> 0 for idle lanes
        const int b = act ? (int)((const unsigned char*)s_lut4)[k] : 0;
        const float a = __shfl_sync(0xffffffffu, xv, b & 15, 16);
        const float c = __shfl_sync(0xffffffffu, xv, b >> 4, 16);
        const float ex = __expf(tvk);
        den += ex;
        num = fmaf(ex, fminf(a, c), num);
    }

    // butterfly reduction within each 16-lane half
#pragma unroll
    for (int o = 8; o > 0; o >>= 1) {
        num += __shfl_xor_sync(0xffffffffu, num, o);
        den += __shfl_xor_sync(0xffffffffu, den, o);
    }
    return __fdividef(num, den);
}

__global__ void __launch_bounds__(256)
choquet_level2_kernel(const float* __restrict__ vals,
                      const float* __restrict__ theta,
                      float* __restrict__ out,
                      int n_nodes)
{
    __shared__ unsigned int s_lut4[34];
    fill_lut(s_lut4);
    __syncthreads();

    const int gw   = (int)((blockIdx.x * blockDim.x + threadIdx.x) >> 5);
    const int lane = threadIdx.x & 31;
    const int node = gw * 2 + (lane >> 4);
    if (node >= n_nodes) return;               // n_nodes even -> warp-uniform

    const float xv = __ldg(&vals[gw * 32 + lane]);   // 128B coalesced: both nodes' children
    const float r  = choquet_warp2(xv, theta + (size_t)node * NTH, s_lut4);
    if ((lane & 15) == 0) out[node] = r;
}

// Levels 5 (16 nodes) + 6 (root) fused in one block.
__global__ void __launch_bounds__(256)
choquet_l56_kernel(const float* __restrict__ v4,    // 256 level-4 outputs
                   const float* __restrict__ th5,   // 16 x 136
                   const float* __restrict__ th6,   // 1 x 136
                   float* __restrict__ out)
{
    __shared__ unsigned int s_lut4[34];
    __shared__ float s5[16];
    fill_lut(s_lut4);
    __syncthreads();

    const int warp = threadIdx.x >> 5;
    const int lane = threadIdx.x & 31;
    const int node = warp * 2 + (lane >> 4);

    const float xv = v4[warp * 32 + lane];
    const float r  = choquet_warp2(xv, th5 + (size_t)node * NTH, s_lut4);
    if ((lane & 15) == 0) s5[node] = r;
    __syncthreads();

    if (warp == 0) {
        const float x2 = s5[lane & 15];              // both halves mirror the root node
        const float root = choquet_warp2(x2, th6, s_lut4);
        if (lane == 0) out[0] = root;
    }
}

static inline void launch_level(const float* vals, const float* theta,
                                float* out, int n_nodes)
{
    const int blocks = n_nodes / 16;           // 8 warps/block, 2 nodes/warp
    choquet_level2_kernel<<<blocks > 0 ? blocks : 1, 256>>>(vals, theta, out, n_nodes);
}

extern "C" void kernel_launch(void* const* d_in, const int* in_sizes, int n_in,
                              void* d_out, int out_size)
{
    (void)in_sizes; (void)n_in; (void)out_size;

    const float* x   = (const float*)d_in[0];
    const float* th1 = (const float*)d_in[1];
    const float* th2 = (const float*)d_in[2];
    const float* th3 = (const float*)d_in[3];
    const float* th4 = (const float*)d_in[4];
    const float* th5 = (const float*)d_in[5];
    const float* th6 = (const float*)d_in[6];
    float* out = (float*)d_out;

    float *b0, *b1;
    cudaGetSymbolAddress((void**)&b0, g_buf0);
    cudaGetSymbolAddress((void**)&b1, g_buf1);

    launch_level(x,  th1, b0, 1 << 20);   // level 1: 1,048,576 nodes
    launch_level(b0, th2, b1, 1 << 16);   // level 2: 65,536
    launch_level(b1, th3, b0, 1 << 12);   // level 3: 4,096
    launch_level(b0, th4, b1, 1 << 8);    // level 4: 256
    choquet_l56_kernel<<<1, 256>>>(b1, th5, th6, out);   // levels 5+6
}

// round 6
// speedup vs baseline: 26.0139x; 1.1420x over previous
#include <cuda_runtime.h>

// Hierarchical 2-additive Choquet integral, B=16, DEPTH=6.
// Big levels: 4 nodes per warp (two 16-lane halves x two pairs), loads front-batched
// for MLP. Theta row = 136 floats = 544 B (16B aligned per row): 2 float4 passes
// (128 thetas) + 8-lane scalar pass. Pair LUT nibble-packed in smem.

#define NTH 136

__device__ float g_buf0[1 << 20];
__device__ float g_buf1[1 << 16];

__device__ __forceinline__ void fill_lut(unsigned int* s_lut4)
{
    const int t = threadIdx.x;
    if (t < NTH) {
        int i, j;
        if (t < 16) { i = t; j = t; }           // singleton -> min(x_k,x_k)=x_k
        else {
            int rem = t - 16; i = 0;
            #pragma unroll 1
            while (rem >= 15 - i) { rem -= 15 - i; ++i; }
            j = i + 1 + rem;                    // triu row-major == np.triu_indices
        }
        ((unsigned char*)s_lut4)[t] = (unsigned char)(i | (j << 4));
    }
}

// Accumulate 4 thetas (one float4) worth of weighted mins for this half-warp.
__device__ __forceinline__ void accum4(float xv, float4 tv, unsigned int pk,
                                       float& num, float& den)
{
#pragma unroll
    for (int e = 0; e < 4; ++e) {
        const float tvk = (e == 0) ? tv.x : (e == 1) ? tv.y : (e == 2) ? tv.z : tv.w;
        const int b = (pk >> (8 * e)) & 0xff;
        const float a = __shfl_sync(0xffffffffu, xv, b & 15, 16);
        const float c = __shfl_sync(0xffffffffu, xv, b >> 4, 16);
        const float ex = __expf(tvk);
        den += ex;
        num = fmaf(ex, fminf(a, c), num);
    }
}

// Scalar leftover k=128..135 (8 lanes active per half).
__device__ __forceinline__ void accum_tail(float xv, float sc, unsigned int lb,
                                           float& num, float& den)
{
    const float a = __shfl_sync(0xffffffffu, xv, lb & 15, 16);
    const float c = __shfl_sync(0xffffffffu, xv, lb >> 4, 16);
    const float ex = __expf(sc);            // sc = -1e30f on idle lanes -> ex = 0
    den += ex;
    num = fmaf(ex, fminf(a, c), num);
}

// ---------------------------------------------------------------------------
// Big-level kernel: 4 nodes per warp, all global loads issued up front.
// Requires n_nodes % 4 == 0.
// ---------------------------------------------------------------------------
__global__ void __launch_bounds__(256)
choquet4_kernel(const float* __restrict__ vals,
                const float* __restrict__ theta,
                float* __restrict__ out,
                int n_nodes)
{
    __shared__ unsigned int s_lut4[34];
    fill_lut(s_lut4);
    __syncthreads();

    const int gw   = (int)((blockIdx.x * blockDim.x + threadIdx.x) >> 5);
    const int n0   = gw * 4;
    if (n0 >= n_nodes) return;
    const int lane = threadIdx.x & 31;
    const int hl   = lane & 15;
    const int hi   = lane >> 4;

    // ---- front-batched loads (8 independent LDGs) ----
    const float xv0 = __ldg(&vals[n0 * 16 + lane]);        // children of nodes n0, n0+1
    const float xv1 = __ldg(&vals[n0 * 16 + 32 + lane]);   // children of nodes n0+2, n0+3

    const float* thb = theta + (size_t)n0 * NTH;
    const float* rowA = thb + (size_t)hi * NTH;            // pair 0: node n0+hi
    const float* rowB = thb + (size_t)(2 + hi) * NTH;      // pair 1: node n0+2+hi
    const float4 t00 = __ldg(&((const float4*)rowA)[hl]);
    const float4 t01 = __ldg(&((const float4*)rowA)[hl + 16]);
    const float4 t10 = __ldg(&((const float4*)rowB)[hl]);
    const float4 t11 = __ldg(&((const float4*)rowB)[hl + 16]);
    const bool act = hl < 8;
    const float s0 = act ? __ldg(&rowA[128 + hl]) : -1e30f;
    const float s1 = act ? __ldg(&rowB[128 + hl]) : -1e30f;

    // ---- LUT words ----
    const unsigned int pkA = s_lut4[hl];
    const unsigned int pkB = s_lut4[hl + 16];
    const unsigned int lbT = act ? ((const unsigned char*)s_lut4)[128 + hl] : 0u;

    // ---- pair 0 ----
    float num0 = 0.f, den0 = 0.f;
    accum4(xv0, t00, pkA, num0, den0);
    accum4(xv0, t01, pkB, num0, den0);
    accum_tail(xv0, s0, lbT, num0, den0);

    // ---- pair 1 ----
    float num1 = 0.f, den1 = 0.f;
    accum4(xv1, t10, pkA, num1, den1);
    accum4(xv1, t11, pkB, num1, den1);
    accum_tail(xv1, s1, lbT, num1, den1);

    // ---- reductions within each 16-lane half ----
#pragma unroll
    for (int o = 8; o > 0; o >>= 1) {
        num0 += __shfl_xor_sync(0xffffffffu, num0, o);
        den0 += __shfl_xor_sync(0xffffffffu, den0, o);
        num1 += __shfl_xor_sync(0xffffffffu, num1, o);
        den1 += __shfl_xor_sync(0xffffffffu, den1, o);
    }

    if (hl == 0) {
        out[n0 + hi]     = __fdividef(num0, den0);
        out[n0 + 2 + hi] = __fdividef(num1, den1);
    }
}

// ---------------------------------------------------------------------------
// Fused tail: levels 4 (256), 5 (16), 6 (1) in one 1024-thread block.
// Two nodes per warp per iteration.
// ---------------------------------------------------------------------------
__device__ __forceinline__ float choquet_warp2(float xv, const float* __restrict__ th,
                                               const unsigned int* s_lut4)
{
    const int hl = threadIdx.x & 15;
    float num = 0.f, den = 0.f;
    accum4(xv, __ldg(&((const float4*)th)[hl]),      s_lut4[hl],      num, den);
    accum4(xv, __ldg(&((const float4*)th)[hl + 16]), s_lut4[hl + 16], num, den);
    const bool act = hl < 8;
    accum_tail(xv, act ? __ldg(&th[128 + hl]) : -1e30f,
               act ? ((const unsigned char*)s_lut4)[128 + hl] : 0u, num, den);
#pragma unroll
    for (int o = 8; o > 0; o >>= 1) {
        num += __shfl_xor_sync(0xffffffffu, num, o);
        den += __shfl_xor_sync(0xffffffffu, den, o);
    }
    return __fdividef(num, den);
}

__global__ void __launch_bounds__(1024)
choquet_tail_kernel(const float* __restrict__ v3,    // 4096 level-3 outputs
                    const float* __restrict__ th4,   // 256 x 136
                    const float* __restrict__ th5,   // 16 x 136
                    const float* __restrict__ th6,   // 1 x 136
                    float* __restrict__ out)
{
    __shared__ unsigned int s_lut4[34];
    __shared__ float s4[256];
    __shared__ float s5[16];
    fill_lut(s_lut4);
    __syncthreads();

    const int warp = threadIdx.x >> 5;   // 0..31
    const int lane = threadIdx.x & 31;
    const int hi   = lane >> 4;

    // level 4: 256 nodes, 64 per pass (32 warps x 2 nodes), 4 passes
#pragma unroll
    for (int it = 0; it < 4; ++it) {
        const int node = it * 64 + warp * 2 + hi;
        const float xv = __ldg(&v3[it * 1024 + warp * 32 + lane]);
        const float r  = choquet_warp2(xv, th4 + (size_t)node * NTH, s_lut4);
        if ((lane & 15) == 0) s4[node] = r;
    }
    __syncthreads();

    // level 5: 16 nodes on warps 0..7
    if (warp < 8) {
        const int node = warp * 2 + hi;
        const float xv = s4[warp * 32 + lane];
        const float r  = choquet_warp2(xv, th5 + (size_t)node * NTH, s_lut4);
        if ((lane & 15) == 0) s5[node] = r;
    }
    __syncthreads();

    // level 6: root on warp 0 (both halves mirror it)
    if (warp == 0) {
        const float xv = s5[lane & 15];
        const float root = choquet_warp2(xv, th6, s_lut4);
        if (lane == 0) out[0] = root;
    }
}

static inline void launch_level(const float* vals, const float* theta,
                                float* out, int n_nodes)
{
    const int warps = n_nodes / 4;                 // 4 nodes per warp
    const int blocks = (warps + 7) / 8;            // 8 warps per block
    choquet4_kernel<<<blocks, 256>>>(vals, theta, out, n_nodes);
}

extern "C" void kernel_launch(void* const* d_in, const int* in_sizes, int n_in,
                              void* d_out, int out_size)
{
    (void)in_sizes; (void)n_in; (void)out_size;

    const float* x   = (const float*)d_in[0];
    const float* th1 = (const float*)d_in[1];
    const float* th2 = (const float*)d_in[2];
    const float* th3 = (const float*)d_in[3];
    const float* th4 = (const float*)d_in[4];
    const float* th5 = (const float*)d_in[5];
    const float* th6 = (const float*)d_in[6];
    float* out = (float*)d_out;

    float *b0, *b1;
    cudaGetSymbolAddress((void**)&b0, g_buf0);
    cudaGetSymbolAddress((void**)&b1, g_buf1);

    launch_level(x,  th1, b0, 1 << 20);   // level 1: 1,048,576 nodes
    launch_level(b0, th2, b1, 1 << 16);   // level 2: 65,536
    launch_level(b1, th3, b0, 1 << 12);   // level 3: 4,096
    choquet_tail_kernel<<<1, 1024>>>(b0, th4, th5, th6, out);   // levels 4-6
}